// round 9
// baseline (speedup 1.0000x reference)
#include <cuda_runtime.h>
#include <cstdint>
#include <climits>

#define Bn 64
#define Hn 512
#define Wn 512
#define HWn (Hn * Wn)
#define CTAS_PER_BATCH 4
#define GRID (Bn * CTAS_PER_BATCH)          // 256 — single wave, 2 CTAs/SM (smem-limited)
#define ROWS_PER_CTA (Hn / CTAS_PER_BATCH)  // 128
#define STAGE_ROWS 4
#define NSTAGES (ROWS_PER_CTA / STAGE_ROWS) // 32
#define NBUF 4
#define STAGE_CH_BYTES (STAGE_ROWS * Wn * 4)   // 8192
#define STAGE_BYTES (3 * STAGE_CH_BYTES)       // 24576
#define SMEM_BUFS (NBUF * STAGE_BYTES)         // 98304
#define SMEM_MBAR SMEM_BUFS                    // 4 x u64
#define SMEM_TAIL (SMEM_MBAR + 64)             // reduction scratch
#define SMEM_TOTAL (SMEM_TAIL + 256)

// Per-CTA partials — overwritten every launch before being read.
__device__ float              g_s1[GRID], g_s2[GRID];
__device__ unsigned long long g_m1e[GRID], g_m1o[GRID], g_m2e[GRID], g_m2o[GRID];
__device__ unsigned           g_count[Bn];

__device__ __forceinline__ uint32_t smem_u32(const void* p) {
    uint32_t a;
    asm("{ .reg .u64 t; cvta.to.shared.u64 t, %1; cvt.u32.u64 %0, t; }" : "=r"(a) : "l"(p));
    return a;
}
__device__ __forceinline__ void mbar_init(uint32_t mbar, uint32_t cnt) {
    asm volatile("mbarrier.init.shared.b64 [%0], %1;" :: "r"(mbar), "r"(cnt) : "memory");
}
__device__ __forceinline__ void mbar_expect_tx(uint32_t mbar, uint32_t tx) {
    asm volatile("mbarrier.arrive.expect_tx.shared.b64 _, [%0], %1;" :: "r"(mbar), "r"(tx) : "memory");
}
__device__ __forceinline__ void bulk_g2s(uint32_t dst, const void* src, uint32_t bytes, uint32_t mbar) {
    asm volatile("cp.async.bulk.shared::cluster.global.mbarrier::complete_tx::bytes [%0], [%1], %2, [%3];"
                 :: "r"(dst), "l"(src), "r"(bytes), "r"(mbar) : "memory");
}
__device__ __forceinline__ void mbar_wait(uint32_t mbar, uint32_t parity) {
    uint32_t done;
    asm volatile("{ .reg .pred p; mbarrier.try_wait.parity.acquire.cta.shared::cta.b64 p, [%1], %2; selp.b32 %0, 1, 0, p; }"
                 : "=r"(done) : "r"(mbar), "r"(parity) : "memory");
    while (!done) {
        asm volatile("{ .reg .pred p; mbarrier.try_wait.parity.acquire.cta.shared::cta.b64 p, [%1], %2, 0x989680; selp.b32 %0, 1, 0, p; }"
                     : "=r"(done) : "r"(mbar), "r"(parity) : "memory");
    }
}

__global__ void __launch_bounds__(256) cdr_fused_kernel(const float* __restrict__ x,
                                                        float* __restrict__ out) {
    extern __shared__ unsigned char smem[];
    const int b   = blockIdx.x >> 2;   // batch
    const int c   = blockIdx.x & 3;    // CTA within batch
    const int tid = threadIdx.x;
    const int row0 = c * ROWS_PER_CTA;

    const uint32_t smem_base = smem_u32(smem);
    const uint32_t mbar0 = smem_base + SMEM_MBAR;

    if (tid == 0) {
        for (int k = 0; k < NBUF; k++) mbar_init(mbar0 + 8 * k, 1u);
        asm volatile("fence.proxy.async.shared::cta;" ::: "memory");
    }
    __syncthreads();

    // Prologue: issue stages 0..2
    if (tid == 0) {
#pragma unroll
        for (int k = 0; k < 3; k++) {
            const uint32_t mb = mbar0 + 8 * k;
            mbar_expect_tx(mb, STAGE_BYTES);
#pragma unroll
            for (int ch = 0; ch < 3; ch++) {
                const uint32_t dst = smem_base + (uint32_t)(k * 3 + ch) * STAGE_CH_BYTES;
                const float* src = x + ((size_t)b * 3 + ch) * HWn + (size_t)(row0 + k * STAGE_ROWS) * Wn;
                bulk_g2s(dst, src, STAGE_CH_BYTES, mb);
            }
        }
    }

    float s1 = 0.f, s2 = 0.f;
    unsigned long long m1 = 0ULL, m2 = 0ULL;
    const int rsel = tid >> 7;   // class e: rows stage*4 + rsel + 2j

#pragma unroll 4
    for (int s = 0; s < NSTAGES; s++) {
        const int buf = s & 3;
        mbar_wait(mbar0 + 8 * buf, (s >> 2) & 1);

        const float4* B0 = (const float4*)(smem + (size_t)(buf * 3 + 0) * STAGE_CH_BYTES);
        const float4* B1 = (const float4*)(smem + (size_t)(buf * 3 + 1) * STAGE_CH_BYTES);
        const float4* B2 = (const float4*)(smem + (size_t)(buf * 3 + 2) * STAGE_CH_BYTES);

#pragma unroll
        for (int j = 0; j < 2; j++) {
            const int idx = tid + 256 * j;
            float4 v0 = B0[idx];
            float4 v1 = B1[idx];
            float4 v2 = B2[idx];
            const float* a0p = (const float*)&v0;
            const float* a1p = (const float*)&v1;
            const float* a2p = (const float*)&v2;
            bool any1 = false, any2 = false;
#pragma unroll
            for (int k = 0; k < 4; k++) {
                float a0 = a0p[k], a1 = a1p[k], a2 = a2p[k];
                float m01 = fmaxf(a0, a1);
                bool  l2  = a2 > m01;
                bool  l1  = (a1 > a0) && !l2;
                any1 |= l1;
                any2 |= l2;
                float e0  = __expf(a0 - a1);
                float e2  = __expf(a2 - a1);
                float inv = __fdividef(1.0f, e0 + 1.0f + e2);
                s1 += inv;        // p(cup)
                s2 += e2 * inv;   // p(disc)
            }
            const int bit = 2 * s + j;     // row_local = 2*bit + rsel
            if (any1) m1 |= 1ULL << bit;
            if (any2) m2 |= 1ULL << bit;
        }

        __syncthreads();
        if (s + 3 < NSTAGES && tid == 0) {
            const int k = s + 3, kb = k & 3;
            const uint32_t mb = mbar0 + 8 * kb;
            mbar_expect_tx(mb, STAGE_BYTES);
#pragma unroll
            for (int ch = 0; ch < 3; ch++) {
                const uint32_t dst = smem_base + (uint32_t)(kb * 3 + ch) * STAGE_CH_BYTES;
                const float* src = x + ((size_t)b * 3 + ch) * HWn + (size_t)(row0 + k * STAGE_ROWS) * Wn;
                bulk_g2s(dst, src, STAGE_CH_BYTES, mb);
            }
        }
    }

    // ---- deterministic in-warp reduction (all lanes in a warp share rsel) ----
#pragma unroll
    for (int o = 16; o > 0; o >>= 1) {
        s1 += __shfl_xor_sync(0xFFFFFFFFu, s1, o);
        s2 += __shfl_xor_sync(0xFFFFFFFFu, s2, o);
        m1 |= __shfl_xor_sync(0xFFFFFFFFu, m1, o);
        m2 |= __shfl_xor_sync(0xFFFFFFFFu, m2, o);
    }

    float*              sw1 = (float*)(smem + SMEM_TAIL);
    float*              sw2 = (float*)(smem + SMEM_TAIL + 32);
    unsigned long long* sm1 = (unsigned long long*)(smem + SMEM_TAIL + 64);
    unsigned long long* sm2 = (unsigned long long*)(smem + SMEM_TAIL + 128);
    const int wid = tid >> 5, lid = tid & 31;
    if (lid == 0) { sw1[wid] = s1; sw2[wid] = s2; sm1[wid] = m1; sm2[wid] = m2; }
    __syncthreads();
    if (wid != 0) return;   // 7 of 8 warps retire

    float pv1 = (lid < 8) ? sw1[lid] : 0.f;
    float pv2 = (lid < 8) ? sw2[lid] : 0.f;
    unsigned long long pm1 = (lid < 8) ? sm1[lid] : 0ULL;   // lanes 0-3: e=0 warps; 4-7: e=1
    unsigned long long pm2 = (lid < 8) ? sm2[lid] : 0ULL;
#pragma unroll
    for (int o = 4; o > 0; o >>= 1) {
        pv1 += __shfl_xor_sync(0xFFFFFFFFu, pv1, o);
        pv2 += __shfl_xor_sync(0xFFFFFFFFu, pv2, o);
    }
    // masks: merge within each class group of 4 lanes only
    pm1 |= __shfl_xor_sync(0xFFFFFFFFu, pm1, 1);
    pm1 |= __shfl_xor_sync(0xFFFFFFFFu, pm1, 2);
    pm2 |= __shfl_xor_sync(0xFFFFFFFFu, pm2, 1);
    pm2 |= __shfl_xor_sync(0xFFFFFFFFu, pm2, 2);
    unsigned long long m1o_ = __shfl_sync(0xFFFFFFFFu, pm1, 4);  // class e=1
    unsigned long long m2o_ = __shfl_sync(0xFFFFFFFFu, pm2, 4);

    int lastFlag = 0;
    if (lid == 0) {
        g_s1[blockIdx.x]  = pv1;
        g_s2[blockIdx.x]  = pv2;
        g_m1e[blockIdx.x] = pm1;    // lane0 holds class e=0 merge
        g_m1o[blockIdx.x] = m1o_;
        g_m2e[blockIdx.x] = pm2;
        g_m2o[blockIdx.x] = m2o_;
        __threadfence();
        lastFlag = (atomicAdd(&g_count[b], 1u) == CTAS_PER_BATCH - 1);
    }
    lastFlag = __shfl_sync(0xFFFFFFFFu, lastFlag, 0);
    if (!lastFlag) return;

    // ---- elected warp finalizes batch b: 4 CTA partials on lanes 0..3 ----
    float t1 = 0.f, t2 = 0.f;
    int mn1 = INT_MAX, mx1 = -1, mn2 = INT_MAX, mx2 = -1;
    if (lid < CTAS_PER_BATCH) {
        const int idx = b * CTAS_PER_BATCH + lid;
        t1 = __ldcg(&g_s1[idx]);
        t2 = __ldcg(&g_s2[idx]);
        unsigned long long e1 = __ldcg(&g_m1e[idx]), o1 = __ldcg(&g_m1o[idx]);
        unsigned long long e2 = __ldcg(&g_m2e[idx]), o2 = __ldcg(&g_m2o[idx]);
        const int base = lid * ROWS_PER_CTA;
        if (e1) { mn1 = min(mn1, base + 2 * (__ffsll(e1) - 1));
                  mx1 = max(mx1, base + 2 * (63 - __clzll(e1))); }
        if (o1) { mn1 = min(mn1, base + 2 * (__ffsll(o1) - 1) + 1);
                  mx1 = max(mx1, base + 2 * (63 - __clzll(o1)) + 1); }
        if (e2) { mn2 = min(mn2, base + 2 * (__ffsll(e2) - 1));
                  mx2 = max(mx2, base + 2 * (63 - __clzll(e2))); }
        if (o2) { mn2 = min(mn2, base + 2 * (__ffsll(o2) - 1) + 1);
                  mx2 = max(mx2, base + 2 * (63 - __clzll(o2)) + 1); }
    }
#pragma unroll
    for (int o = 2; o > 0; o >>= 1) {
        t1  += __shfl_xor_sync(0xFFFFFFFFu, t1, o);
        t2  += __shfl_xor_sync(0xFFFFFFFFu, t2, o);
        mn1  = min(mn1, __shfl_xor_sync(0xFFFFFFFFu, mn1, o));
        mx1  = max(mx1, __shfl_xor_sync(0xFFFFFFFFu, mx1, o));
        mn2  = min(mn2, __shfl_xor_sync(0xFFFFFFFFu, mn2, o));
        mx2  = max(mx2, __shfl_xor_sync(0xFFFFFFFFu, mx2, o));
    }

    if (lid == 0) {
        const float inv_hw = 1.0f / (float)HWn;
        float cup_mean  = t1 * inv_hw;
        float disc_mean = t2 * inv_hw;
        float hcup  = (mx1 >= 0) ? (float)(mx1 - mn1) : 0.0f;
        float hdisc = (mx2 >= 0) ? (float)(mx2 - mn2) : 0.0f;
        float cdr = hcup / (hdisc + 1e-6f);
        out[b * 5 + 0] = cdr;
        out[b * 5 + 1] = disc_mean;
        out[b * 5 + 2] = cup_mean;
        out[b * 5 + 3] = disc_mean;
        out[b * 5 + 4] = cup_mean;
        g_count[b] = 0;   // self-reset: deterministic across graph replays
    }
}

extern "C" void kernel_launch(void* const* d_in, const int* in_sizes, int n_in,
                              void* d_out, int out_size) {
    const float* x = (const float*)d_in[0];
    float* out = (float*)d_out;
    (void)in_sizes; (void)n_in; (void)out_size;

    cudaFuncSetAttribute(cdr_fused_kernel,
                         cudaFuncAttributeMaxDynamicSharedMemorySize, SMEM_TOTAL);
    cdr_fused_kernel<<<GRID, 256, SMEM_TOTAL>>>(x, out);
}